// round 10
// baseline (speedup 1.0000x reference)
#include <cuda_runtime.h>
#include <math.h>

// HawkesPointProcess: B=8, N=4096. One CTA per batch row, 1024 threads (32
// warps), 4 elements/thread. Shuffle affine scan; redundant cross-warp scan
// (2 barriers total); single fused scalar reduction.
//
//   A_i = e_i*(A_{i-1}+1), e_i = exp(-beta*(t_i - t_{i-1})), e_0 := 0
//   lamb_i = A_i*alpha*beta + mu
//   out[b] = sum_i log(lamb_i+1e-8)*m_i + alpha*(sum_i exp(log_kernel_i) - sum_i m_i)
//            - (t1-t0)*mu
//   (algebraically identical to reference: out = loglik - compensator)

#define NT 1024
#define NW 32        // warps per CTA == lanes, enables full-width redundant scan
#define CHUNK 4      // NT*CHUNK == N == 4096

__device__ __forceinline__ float softplus_fast(float x) {
    return __logf(1.0f + __expf(x));   // |x| ~ 0.3 -> rel err ~1e-6
}

__global__ __launch_bounds__(NT, 1)
void hawkes_kernel(const float* __restrict__ et,
                   const float* __restrict__ mask,
                   const float* __restrict__ t0v,
                   const float* __restrict__ t1v,
                   const float* __restrict__ mu_raw,
                   const float* __restrict__ alpha_raw,
                   const float* __restrict__ beta_raw,
                   float* __restrict__ out,
                   int N) {
    const int b    = blockIdx.x;
    const int tid  = threadIdx.x;
    const int lane = tid & 31;
    const int warp = tid >> 5;

    const float mu    = softplus_fast(mu_raw[0]);
    const float alpha = softplus_fast(alpha_raw[0]);
    const float beta  = softplus_fast(beta_raw[0]);
    const float T1    = t1v[b];

    const float* t = et   + (size_t)b * N;
    const float* m = mask + (size_t)b * N;

    __shared__ float2 sGH[NW];    // per-warp (G,H) aggregates
    __shared__ float  rv[NW];     // per-warp fused partials

    const int base = tid * CHUNK;

    // Coalesced vector loads (tprev overlaps with them — independent LDG).
    const float4 t4 = *reinterpret_cast<const float4*>(t + base);
    const float4 m4 = *reinterpret_cast<const float4*>(m + base);
    const float tprev = (tid == 0) ? t4.x : t[base - 1];

    // Per-element decay factors (4 independent MUFU exps).
    float e0 = __expf(-beta * (t4.x - tprev));
    const float e1 = __expf(-beta * (t4.y - t4.x));
    const float e2 = __expf(-beta * (t4.z - t4.y));
    const float e3 = __expf(-beta * (t4.w - t4.z));
    if (tid == 0) e0 = 0.0f;   // global element 0: A_0 = 0

    // Per-element affine coefficients within the chunk: A_k = P_k*A_in + H_k.
    const float P0 = e0,      H0 = e0;
    const float P1 = e1 * P0; const float H1 = fmaf(e1, H0, e1);
    const float P2 = e2 * P1; const float H2 = fmaf(e2, H1, e2);
    const float P3 = e3 * P2; const float H3 = fmaf(e3, H2, e3);

    float G = P3, H = H3;

    // Independent partials (comp + mask), exact reference formula per element.
    const float comp =
        __expf(fmaf(-beta * (T1 - t4.x), m4.x, (1.0f - m4.x) * (-1e20f))) +
        __expf(fmaf(-beta * (T1 - t4.y), m4.y, (1.0f - m4.y) * (-1e20f))) +
        __expf(fmaf(-beta * (T1 - t4.z), m4.z, (1.0f - m4.z) * (-1e20f))) +
        __expf(fmaf(-beta * (T1 - t4.w), m4.w, (1.0f - m4.w) * (-1e20f)));
    const float msum = (m4.x + m4.y) + (m4.z + m4.w);

    // Inclusive warp scan over (G,H): compose(cur, prev) = (Gc*Gp, Gc*Hp+Hc).
    #pragma unroll
    for (int off = 1; off < 32; off <<= 1) {
        const float Gp = __shfl_up_sync(0xffffffffu, G, off);
        const float Hp = __shfl_up_sync(0xffffffffu, H, off);
        if (lane >= off) { H = fmaf(G, Hp, H); G *= Gp; }
    }
    // Lane-exclusive transform within warp.
    float Gex = __shfl_up_sync(0xffffffffu, G, 1);
    float Hex = __shfl_up_sync(0xffffffffu, H, 1);
    if (lane == 0) { Gex = 1.0f; Hex = 0.0f; }

    if (lane == 31) sGH[warp] = make_float2(G, H);
    __syncthreads();                                          // BAR 1

    // Redundant cross-warp scan: EVERY warp scans all 32 aggregates itself
    // (no second barrier, no warp0 serialization bubble).
    float Aw;
    {
        const float2 a = sGH[lane];
        float g = a.x, h = a.y;
        #pragma unroll
        for (int off = 1; off < 32; off <<= 1) {
            const float gp = __shfl_up_sync(0xffffffffu, g, off);
            const float hp = __shfl_up_sync(0xffffffffu, h, off);
            if (lane >= off) { h = fmaf(g, hp, h); g *= gp; }
        }
        // State entering this warp = inclusive prefix of warp-1 applied to 0.
        const float hprev = __shfl_sync(0xffffffffu, h, (warp == 0) ? 0 : warp - 1);
        Aw = (warp == 0) ? 0.0f : hprev;
    }

    // Per-element states: 4 INDEPENDENT FMAs once A_in is known.
    const float A_in = fmaf(Gex, Aw, Hex);
    const float A0v = fmaf(P0, A_in, H0);
    const float A1v = fmaf(P1, A_in, H1);
    const float A2v = fmaf(P2, A_in, H2);
    const float A3v = fmaf(P3, A_in, H3);

    const float ab = alpha * beta;
    const float l0 = fmaf(A0v, ab, mu) + 1e-8f;
    const float l1 = fmaf(A1v, ab, mu) + 1e-8f;
    const float l2 = fmaf(A2v, ab, mu) + 1e-8f;
    const float l3 = fmaf(A3v, ab, mu) + 1e-8f;
    // lamb^m for m in {0,1}: factor = m*(lamb-1)+1 ; product tree, single log.
    const float f0 = fmaf(m4.x, l0 - 1.0f, 1.0f);
    const float f1 = fmaf(m4.y, l1 - 1.0f, 1.0f);
    const float f2 = fmaf(m4.z, l2 - 1.0f, 1.0f);
    const float f3 = fmaf(m4.w, l3 - 1.0f, 1.0f);
    const float P  = (f0 * f1) * (f2 * f3);

    // Fused per-thread scalar: v = sum log(lamb)*m + alpha*(comp - msum).
    float v = fmaf(alpha, comp - msum, __logf(P));

    // Single-scalar reductions.
    #pragma unroll
    for (int off = 16; off > 0; off >>= 1)
        v += __shfl_xor_sync(0xffffffffu, v, off);
    if (lane == 0) rv[warp] = v;
    __syncthreads();                                          // BAR 2

    if (warp == 0) {
        float s = rv[lane];
        #pragma unroll
        for (int off = 16; off > 0; off >>= 1)
            s += __shfl_xor_sync(0xffffffffu, s, off);
        if (lane == 0) {
            const float T0 = t0v[b];
            out[b] = s - (T1 - T0) * mu;
        }
    }
}

extern "C" void kernel_launch(void* const* d_in, const int* in_sizes, int n_in,
                              void* d_out, int out_size) {
    const float* event_times = (const float*)d_in[0];
    const float* input_mask  = (const float*)d_in[1];
    const float* t0          = (const float*)d_in[2];
    const float* t1          = (const float*)d_in[3];
    const float* mu          = (const float*)d_in[4];
    const float* alpha       = (const float*)d_in[5];
    const float* beta        = (const float*)d_in[6];
    float* out = (float*)d_out;

    const int B = in_sizes[2];      // t0 has B elements
    const int N = in_sizes[0] / B;  // 4096

    hawkes_kernel<<<B, NT>>>(event_times, input_mask, t0, t1,
                             mu, alpha, beta, out, N);
}

// round 11
// speedup vs baseline: 1.3131x; 1.3131x over previous
#include <cuda_runtime.h>
#include <math.h>

// HawkesPointProcess: B=8, N=4096. One CTA per batch row, 1024 threads (32
// warps), 4 elements/thread. R7 skeleton (warp0-only mid scan, 3 barriers) +
// fused single-scalar reduction + independent per-element replay.
//
//   A_i = e_i*(A_{i-1}+1), e_i = exp(-beta*(t_i - t_{i-1})), e_0 := 0
//   lamb_i = A_i*alpha*beta + mu
//   out[b] = sum_i log(lamb_i+1e-8)*m_i + alpha*(sum_i exp(log_kernel_i) - sum_i m_i)
//            - (t1-t0)*mu      (identical algebra to the reference)

#define NT 1024
#define NW 32
#define CHUNK 4      // NT*CHUNK == N == 4096

__device__ __forceinline__ float softplus_fast(float x) {
    return __logf(1.0f + __expf(x));   // |x| ~ 0.3 -> rel err ~1e-6
}

__global__ __launch_bounds__(NT, 1)
void hawkes_kernel(const float* __restrict__ et,
                   const float* __restrict__ mask,
                   const float* __restrict__ t0v,
                   const float* __restrict__ t1v,
                   const float* __restrict__ mu_raw,
                   const float* __restrict__ alpha_raw,
                   const float* __restrict__ beta_raw,
                   float* __restrict__ out,
                   int N) {
    const int b    = blockIdx.x;
    const int tid  = threadIdx.x;
    const int lane = tid & 31;
    const int warp = tid >> 5;

    const float mu    = softplus_fast(mu_raw[0]);
    const float alpha = softplus_fast(alpha_raw[0]);
    const float beta  = softplus_fast(beta_raw[0]);
    const float T1    = t1v[b];

    const float* t = et   + (size_t)b * N;
    const float* m = mask + (size_t)b * N;

    __shared__ float sG[NW], sH[NW];
    __shared__ float rv[NW];

    const int base = tid * CHUNK;

    // Coalesced vector loads; tprev is an independent LDG issued alongside.
    const float4 t4 = *reinterpret_cast<const float4*>(t + base);
    const float4 m4 = *reinterpret_cast<const float4*>(m + base);
    const float tprev = (tid == 0) ? t4.x : t[base - 1];

    // Per-element decay factors (4 independent MUFU exps).
    float e0 = __expf(-beta * (t4.x - tprev));
    const float e1 = __expf(-beta * (t4.y - t4.x));
    const float e2 = __expf(-beta * (t4.z - t4.y));
    const float e3 = __expf(-beta * (t4.w - t4.z));
    if (tid == 0) e0 = 0.0f;   // global element 0: A_0 = 0

    // Per-element affine coefficients: A_k = P_k*A_in + H_k (replay is then
    // 4 independent FMAs once A_in arrives, not an 8-deep chain).
    const float P0 = e0,      H0 = e0;
    const float P1 = e1 * P0; const float H1 = fmaf(e1, H0, e1);
    const float P2 = e2 * P1; const float H2 = fmaf(e2, H1, e2);
    const float P3 = e3 * P2; const float H3 = fmaf(e3, H2, e3);

    float G = P3, H = H3;

    // Independent compensator/mask partials — hoisted here so the MUFU work
    // overlaps the shuffle-scan latency below.
    const float comp =
        __expf(fmaf(-beta * (T1 - t4.x), m4.x, (1.0f - m4.x) * (-1e20f))) +
        __expf(fmaf(-beta * (T1 - t4.y), m4.y, (1.0f - m4.y) * (-1e20f))) +
        __expf(fmaf(-beta * (T1 - t4.z), m4.z, (1.0f - m4.z) * (-1e20f))) +
        __expf(fmaf(-beta * (T1 - t4.w), m4.w, (1.0f - m4.w) * (-1e20f)));
    const float msum = (m4.x + m4.y) + (m4.z + m4.w);

    // Inclusive warp scan over (G,H): compose(cur, prev) = (Gc*Gp, Gc*Hp+Hc).
    #pragma unroll
    for (int off = 1; off < 32; off <<= 1) {
        const float Gp = __shfl_up_sync(0xffffffffu, G, off);
        const float Hp = __shfl_up_sync(0xffffffffu, H, off);
        if (lane >= off) { H = fmaf(G, Hp, H); G *= Gp; }
    }
    // Lane-exclusive transform within warp.
    float Gex = __shfl_up_sync(0xffffffffu, G, 1);
    float Hex = __shfl_up_sync(0xffffffffu, H, 1);
    if (lane == 0) { Gex = 1.0f; Hex = 0.0f; }

    // Warp aggregates -> smem; warp0 alone scans them (cheap: waiting warps
    // park at the barrier instead of burning the SHFL pipe).
    if (lane == 31) { sG[warp] = G; sH[warp] = H; }
    __syncthreads();                                          // BAR 1
    if (warp == 0) {
        float g = sG[lane], h = sH[lane];
        #pragma unroll
        for (int off = 1; off < 32; off <<= 1) {
            const float gp = __shfl_up_sync(0xffffffffu, g, off);
            const float hp = __shfl_up_sync(0xffffffffu, h, off);
            if (lane >= off) { h = fmaf(g, hp, h); g *= gp; }
        }
        sH[lane] = h;   // inclusive warp-prefix values (applied to A=0)
    }
    __syncthreads();                                          // BAR 2

    // State entering this thread's chunk.
    const float Aw   = (warp == 0) ? 0.0f : sH[warp - 1];
    const float A_in = fmaf(Gex, Aw, Hex);

    // Replay: 4 independent FMAs, product tree, single log.
    const float ab = alpha * beta;
    const float l0 = fmaf(fmaf(P0, A_in, H0), ab, mu) + 1e-8f;
    const float l1 = fmaf(fmaf(P1, A_in, H1), ab, mu) + 1e-8f;
    const float l2 = fmaf(fmaf(P2, A_in, H2), ab, mu) + 1e-8f;
    const float l3 = fmaf(fmaf(P3, A_in, H3), ab, mu) + 1e-8f;
    // lamb^m for m in {0,1}: factor = m*(lamb-1)+1.
    const float f0 = fmaf(m4.x, l0 - 1.0f, 1.0f);
    const float f1 = fmaf(m4.y, l1 - 1.0f, 1.0f);
    const float f2 = fmaf(m4.z, l2 - 1.0f, 1.0f);
    const float f3 = fmaf(m4.w, l3 - 1.0f, 1.0f);
    const float P  = (f0 * f1) * (f2 * f3);

    // Fused per-thread scalar: v = sum log(lamb)*m + alpha*(comp - msum).
    float v = fmaf(alpha, comp - msum, __logf(P));

    // Single-scalar two-level reduction.
    #pragma unroll
    for (int off = 16; off > 0; off >>= 1)
        v += __shfl_xor_sync(0xffffffffu, v, off);
    if (lane == 0) rv[warp] = v;
    __syncthreads();                                          // BAR 3

    if (warp == 0) {
        float s = rv[lane];
        #pragma unroll
        for (int off = 16; off > 0; off >>= 1)
            s += __shfl_xor_sync(0xffffffffu, s, off);
        if (lane == 0) {
            const float T0 = t0v[b];
            out[b] = s - (T1 - T0) * mu;
        }
    }
}

extern "C" void kernel_launch(void* const* d_in, const int* in_sizes, int n_in,
                              void* d_out, int out_size) {
    const float* event_times = (const float*)d_in[0];
    const float* input_mask  = (const float*)d_in[1];
    const float* t0          = (const float*)d_in[2];
    const float* t1          = (const float*)d_in[3];
    const float* mu          = (const float*)d_in[4];
    const float* alpha       = (const float*)d_in[5];
    const float* beta        = (const float*)d_in[6];
    float* out = (float*)d_out;

    const int B = in_sizes[2];      // t0 has B elements
    const int N = in_sizes[0] / B;  // 4096

    hawkes_kernel<<<B, NT>>>(event_times, input_mask, t0, t1,
                             mu, alpha, beta, out, N);
}